// round 6
// baseline (speedup 1.0000x reference)
#include <cuda_runtime.h>
#include <cuda_bf16.h>
#include <cstdint>

// Fused: y = AdaptiveAvgPool2d(56)( ReLU(x * std + mean) ), separable 2-pass.
// Single launch; per-CTA uniform dispatch to templated body (S = 24/32/48).
//
// Stage 0: cp.async (LDGSTS.128) flat-coalesced copy of the plane into raw
//   smem (minimal L1 wavefronts, no register staging). S=32 pads the row
//   stride to 36 words so the quarter-row LDS below is bank-conflict-free.
// Stage A: 4 threads/row read their quarter-row from raw smem (conflict-free
//   LDS.128/64), apply affine+ReLU, column-pool to 14 outputs with
//   COMPILE-TIME bins (quarter boundaries exact: col(14q)=qS/4), write
//   T[S][56] (stride 60 words).
// Stage B: out[i][j] = wr*T[r0][j] + w2*T[r0+1][j]; 2x LDS.128 + STG.128.cs
//   per quad. T row S zeroed (w2=0 case reads finite data).

#define TROW 60
#define TPB  196

__device__ __forceinline__ void stcs4(float* p, float4 v) {
    asm volatile("st.global.cs.v4.f32 [%0], {%1,%2,%3,%4};"
                 :: "l"(p), "f"(v.x), "f"(v.y), "f"(v.z), "f"(v.w) : "memory");
}

__device__ __forceinline__ void cp_async16(unsigned int dst, const void* src) {
    asm volatile("cp.async.ca.shared.global [%0], [%1], 16;"
                 :: "r"(dst), "l"(src) : "memory");
}

template<int S>
__device__ __forceinline__
void do_plane(const float* __restrict__ plane, float mean, float sd,
              float* __restrict__ outp, float* __restrict__ raw,
              float* __restrict__ T, int t)
{
    constexpr int NC  = S / 4;                 // floats per quarter-row
    constexpr int STW = (S == 32) ? 36 : S;    // raw row stride (words)

    // ── Stage 0: flat coalesced LDGSTS of the plane into raw smem ──
    {
        const unsigned int rawAddr = (unsigned int)__cvta_generic_to_shared(raw);
        constexpr int F = S * S / 4;           // float4 count
        #pragma unroll
        for (int f0 = 0; f0 < F; f0 += TPB) {
            const int f = f0 + t;
            if (f0 + TPB <= F || f < F) {
                unsigned int dst;
                if constexpr (STW == S) {
                    dst = rawAddr + f * 16;
                } else {
                    const int r = f / NC;      // NC float4s per row
                    const int c = f - r * NC;
                    dst = rawAddr + (unsigned int)(r * STW + c * 4) * 4u;
                }
                cp_async16(dst, (const float4*)plane + f);
            }
        }
        asm volatile("cp.async.commit_group;\n\tcp.async.wait_group 0;" ::: "memory");
    }
    // zero T's guard row while the copy drains
    if (t < TROW) T[S * TROW + t] = 0.0f;
    __syncthreads();

    // ── Stage A: quarter-row LDS + affine + ReLU + column pool ──
    if (t < 4 * S) {
        const int r = t >> 2;
        const int q = t & 3;
        const float* rp = raw + r * STW + q * NC;

        float x[NC];
        if constexpr (NC % 4 == 0) {
            #pragma unroll
            for (int k = 0; k < NC / 4; k++) {
                float4 v = ((const float4*)rp)[k];
                x[4*k+0] = v.x; x[4*k+1] = v.y; x[4*k+2] = v.z; x[4*k+3] = v.w;
            }
        } else {
            #pragma unroll
            for (int k = 0; k < NC / 2; k++) {
                float2 v = ((const float2*)rp)[k];
                x[2*k] = v.x; x[2*k+1] = v.y;
            }
        }
        #pragma unroll
        for (int k = 0; k < NC; k++)
            x[k] = fmaxf(fmaf(x[k], sd, mean), 0.0f);

        float* Trow = &T[r * TROW + q * 14];
        #pragma unroll
        for (int jl = 0; jl < 14; jl += 2) {
            float2 v;
            {
                const int c0  = (jl * S) / 56;
                const int cnt = ((jl + 1) * S + 55) / 56 - c0;
                v.x = (cnt == 1) ? x[c0] : 0.5f * (x[c0] + x[c0 + 1]);
            }
            {
                const int c0  = ((jl + 1) * S) / 56;
                const int cnt = ((jl + 2) * S + 55) / 56 - c0;
                v.y = (cnt == 1) ? x[c0] : 0.5f * (x[c0] + x[c0 + 1]);
            }
            *(float2*)(Trow + jl) = v;
        }
    }
    __syncthreads();

    // ── Stage B: row pool, float4-vectorized; 784 quads = 4 * 196 threads ──
    #pragma unroll
    for (int l = 0; l < 4; l++) {
        const int qd = t + l * TPB;
        const int i  = qd / 14;
        const int j0 = (qd - i * 14) * 4;

        const int r0  = (i * S) / 56;
        const int cnt = ((i + 1) * S + 55) / 56 - r0;
        const float wr = (cnt == 1) ? 1.0f : 0.5f;
        const float w2 = (cnt == 1) ? 0.0f : 0.5f;

        const float4 a = *(const float4*)&T[r0 * TROW + j0];
        const float4 b = *(const float4*)&T[(r0 + 1) * TROW + j0];
        float4 res;
        res.x = fmaf(w2, b.x, wr * a.x);
        res.y = fmaf(w2, b.y, wr * a.y);
        res.z = fmaf(w2, b.z, wr * a.z);
        res.w = fmaf(w2, b.w, wr * a.w);
        stcs4(outp + i * 56 + j0, res);
    }
}

__global__ __launch_bounds__(TPB, 8)
void ppin_fused_kernel(const float* __restrict__ p24,
                       const float* __restrict__ p32,
                       const float* __restrict__ p48,
                       const float* __restrict__ smean,
                       const float* __restrict__ sstd,
                       float* __restrict__ out)
{
    __shared__ float raw[48 * 48];     // staged plane (S=32 uses 32*36)
    __shared__ float T[49 * TROW];     // column-pooled transpose + guard row

    const int bid = blockIdx.x;        // plane = n*256 + c
    const int n   = bid >> 8;
    const int t   = threadIdx.x;

    const float mean = smean[bid];
    const float sd   = sstd[bid];
    float* outp = out + (size_t)bid * 3136;

    if (n < 32) {
        do_plane<24>(p24 + (size_t)bid * (24 * 24), mean, sd, outp, raw, T, t);
    } else if (n < 64) {
        do_plane<32>(p32 + (size_t)(bid - 32 * 256) * (32 * 32), mean, sd, outp, raw, T, t);
    } else {
        do_plane<48>(p48 + (size_t)(bid - 64 * 256) * (48 * 48), mean, sd, outp, raw, T, t);
    }
}

extern "C" void kernel_launch(void* const* d_in, const int* in_sizes, int n_in,
                              void* d_out, int out_size)
{
    const float* p24   = (const float*)d_in[0];
    const float* p32   = (const float*)d_in[1];
    const float* p48   = (const float*)d_in[2];
    const float* smean = (const float*)d_in[3];
    const float* sstd  = (const float*)d_in[4];
    float* out = (float*)d_out;

    ppin_fused_kernel<<<96 * 256, TPB>>>(p24, p32, p48, smean, sstd, out);
}

// round 7
// speedup vs baseline: 1.0871x; 1.0871x over previous
#include <cuda_runtime.h>
#include <cuda_bf16.h>
#include <cstdint>

// Fused: y = AdaptiveAvgPool2d(56)( ReLU(x * std + mean) ), separable 2-pass.
// Single launch; per-CTA uniform dispatch to templated body (S = 24/32/48).
//
// Phase A: 4 threads per input row; each loads S/4 cols from GMEM (LDG.128/64),
//   applies affine+ReLU, column-pools to 14 outputs with COMPILE-TIME bins
//   (quarter boundaries exact: col(14q) = qS/4), writes T[S][56] (stride 60).
// Phase B: out row i = T[r0] (cnt==1, majority) or 0.5*(T[r0]+T[r0+1]);
//   the second LDS.128 is issued ONLY when cnt==2 (warp-coherent branch),
//   cutting ~35% of phase-B shared traffic. STG.128.cs streaming stores.

#define TROW 60   // T row stride in floats (240B, 16B-aligned, conflict-free)
#define TPB  196

__device__ __forceinline__ void stcs4(float* p, float4 v) {
    asm volatile("st.global.cs.v4.f32 [%0], {%1,%2,%3,%4};"
                 :: "l"(p), "f"(v.x), "f"(v.y), "f"(v.z), "f"(v.w) : "memory");
}

template<int S>
__device__ __forceinline__
void do_plane(const float* __restrict__ plane, float mean, float sd,
              float* __restrict__ outp, float* __restrict__ T, int t)
{
    constexpr int NC = S / 4;   // input cols per phase-A thread

    // ── Phase A: load + affine + ReLU + column pool (compile-time bins) ──
    if (t < 4 * S) {
        const int r = t >> 2;
        const int q = t & 3;
        const float* rp = plane + r * S + q * NC;

        float x[NC];
        if constexpr (NC % 4 == 0) {
            #pragma unroll
            for (int k = 0; k < NC / 4; k++) {
                float4 v = ((const float4*)rp)[k];
                x[4*k+0] = v.x; x[4*k+1] = v.y; x[4*k+2] = v.z; x[4*k+3] = v.w;
            }
        } else {
            #pragma unroll
            for (int k = 0; k < NC / 2; k++) {
                float2 v = ((const float2*)rp)[k];
                x[2*k] = v.x; x[2*k+1] = v.y;
            }
        }
        #pragma unroll
        for (int k = 0; k < NC; k++)
            x[k] = fmaxf(fmaf(x[k], sd, mean), 0.0f);

        float* Trow = &T[r * TROW + q * 14];
        #pragma unroll
        for (int jl = 0; jl < 14; jl += 2) {
            float2 v;
            {
                const int c0  = (jl * S) / 56;
                const int cnt = ((jl + 1) * S + 55) / 56 - c0;
                v.x = (cnt == 1) ? x[c0] : 0.5f * (x[c0] + x[c0 + 1]);
            }
            {
                const int c0  = ((jl + 1) * S) / 56;
                const int cnt = ((jl + 2) * S + 55) / 56 - c0;
                v.y = (cnt == 1) ? x[c0] : 0.5f * (x[c0] + x[c0 + 1]);
            }
            *(float2*)(Trow + jl) = v;
        }
    }
    __syncthreads();

    // ── Phase B: row pool; second row load only when the bin spans 2 rows ──
    #pragma unroll
    for (int l = 0; l < 4; l++) {
        const int qd = t + l * TPB;
        const int i  = qd / 14;
        const int j0 = (qd - i * 14) * 4;

        const int r0  = (i * S) / 56;
        const int cnt = ((i + 1) * S + 55) / 56 - r0;

        float4 res = *(const float4*)&T[r0 * TROW + j0];
        if (cnt == 2) {
            const float4 b = *(const float4*)&T[(r0 + 1) * TROW + j0];
            res.x = 0.5f * (res.x + b.x);
            res.y = 0.5f * (res.y + b.y);
            res.z = 0.5f * (res.z + b.z);
            res.w = 0.5f * (res.w + b.w);
        }
        stcs4(outp + i * 56 + j0, res);
    }
}

__global__ __launch_bounds__(TPB, 8)
void ppin_fused_kernel(const float* __restrict__ p24,
                       const float* __restrict__ p32,
                       const float* __restrict__ p48,
                       const float* __restrict__ smean,
                       const float* __restrict__ sstd,
                       float* __restrict__ out)
{
    __shared__ float T[48 * TROW];     // column-pooled intermediate

    const int bid = blockIdx.x;        // plane = n*256 + c
    const int n   = bid >> 8;
    const int t   = threadIdx.x;

    const float mean = smean[bid];
    const float sd   = sstd[bid];
    float* outp = out + (size_t)bid * 3136;

    if (n < 32) {
        do_plane<24>(p24 + (size_t)bid * (24 * 24), mean, sd, outp, T, t);
    } else if (n < 64) {
        do_plane<32>(p32 + (size_t)(bid - 32 * 256) * (32 * 32), mean, sd, outp, T, t);
    } else {
        do_plane<48>(p48 + (size_t)(bid - 64 * 256) * (48 * 48), mean, sd, outp, T, t);
    }
}

extern "C" void kernel_launch(void* const* d_in, const int* in_sizes, int n_in,
                              void* d_out, int out_size)
{
    const float* p24   = (const float*)d_in[0];
    const float* p32   = (const float*)d_in[1];
    const float* p48   = (const float*)d_in[2];
    const float* smean = (const float*)d_in[3];
    const float* sstd  = (const float*)d_in[4];
    float* out = (float*)d_out;

    ppin_fused_kernel<<<96 * 256, TPB>>>(p24, p32, p48, smean, sstd, out);
}